// round 9
// baseline (speedup 1.0000x reference)
#include <cuda_runtime.h>
#include <math.h>

#define BB 128
#define TT 25
#define VOCAB 10000
#define EMBD 512
#define VGGD 4096
#define HIDD 512
#define GBLK 128

// ---------------- scratch (device globals; no allocation allowed) ------------
__device__ float g_h0[BB * HIDD];
__device__ float g_E[TT * BB * EMBD];          // gathered embeddings, row = t*B+b
__device__ float g_X0[TT * BB * 3 * HIDD];     // precomputed layer-0 input proj [u|r|c]
__device__ float g_S1[TT * BB * HIDD];         // s1 per step
__device__ float g_s0buf[2][BB * HIDD];        // s0 double buffer
__device__ float g_gu0[BB * HIDD];
__device__ float g_gr0[BB * HIDD];
__device__ float g_gu1[BB * HIDD];
__device__ float g_gr1[BB * HIDD];
__device__ float g_W0top[HIDD * 3 * HIDD];     // packed [Wu0_top|Wr0_top|Wc0_top]
__device__ float g_b0top[3 * HIDD];
__device__ unsigned g_bar_count;               // zero-init; returns to 0 each launch
__device__ unsigned g_bar_sense;               // toggles; read at kernel start

// ---------------- pack layer-0 top weights -----------------------------------
__global__ void pack_w0top(const float* __restrict__ Wu0, const float* __restrict__ Wr0,
                           const float* __restrict__ Wc0, const float* __restrict__ bu0,
                           const float* __restrict__ br0, const float* __restrict__ bc0) {
    int idx = blockIdx.x * blockDim.x + threadIdx.x;
    const int total = HIDD * 3 * HIDD;
    if (idx < total) {
        int k = idx / (3 * HIDD);
        int j = idx - k * (3 * HIDD);
        float v;
        if (j < HIDD)           v = Wu0[k * HIDD + j];
        else if (j < 2 * HIDD)  v = Wr0[k * HIDD + (j - HIDD)];
        else                    v = Wc0[k * HIDD + (j - 2 * HIDD)];
        g_W0top[idx] = v;
    }
    if (idx < 3 * HIDD) {
        g_b0top[idx] = (idx < HIDD) ? bu0[idx]
                     : (idx < 2 * HIDD) ? br0[idx - HIDD]
                                        : bc0[idx - 2 * HIDD];
    }
}

// ---------------- embedding gather -------------------------------------------
__global__ void embed_gather(const float* __restrict__ emb, const int* __restrict__ tokens) {
    int r = blockIdx.x;              // r = t*B + b
    int t = r / BB;
    int b = r - t * BB;
    int tok = tokens[b * TT + t];
    const float4* src = (const float4*)(emb + (size_t)tok * EMBD);
    float4* dst = (float4*)(g_E + (size_t)r * EMBD);
    dst[threadIdx.x] = src[threadIdx.x];   // 128 threads * float4 = 512 floats
}

// ---------------- big tiled SGEMM: C = A@W + bias ----------------------------
template <int AREMAP>
__global__ __launch_bounds__(256) void sgemm_big(
    const float* __restrict__ A, const float* __restrict__ W,
    const float* __restrict__ bias, float* __restrict__ C,
    int M, int N, int K)
{
    __shared__ float As[8][128];
    __shared__ float Ws[8][128];
    int tid = threadIdx.x;
    int m0 = blockIdx.y * 128;
    int n0 = blockIdx.x * 128;
    int tx = tid & 15;
    int ty = tid >> 4;

    float acc[8][8];
#pragma unroll
    for (int i = 0; i < 8; i++)
#pragma unroll
        for (int j = 0; j < 8; j++) acc[i][j] = 0.f;

    int lar = tid >> 1;
    int lak = (tid & 1) * 4;
    int arow = m0 + lar;
    if (AREMAP) arow = (arow % TT) * BB + (arow / TT);
    const float* Aptr = A + (size_t)arow * K;
    int lwk = tid >> 5;
    int lwc = (tid & 31) * 4;

    for (int k0 = 0; k0 < K; k0 += 8) {
        float4 av = *(const float4*)(Aptr + k0 + lak);
        As[lak + 0][lar] = av.x;
        As[lak + 1][lar] = av.y;
        As[lak + 2][lar] = av.z;
        As[lak + 3][lar] = av.w;

        int wn = n0 + lwc;
        const float* Wp = W + (size_t)(k0 + lwk) * N + wn;
        float4 wv;
        if (wn + 3 < N) {
            wv = *(const float4*)Wp;
        } else {
            wv.x = (wn + 0 < N) ? Wp[0] : 0.f;
            wv.y = (wn + 1 < N) ? Wp[1] : 0.f;
            wv.z = (wn + 2 < N) ? Wp[2] : 0.f;
            wv.w = (wn + 3 < N) ? Wp[3] : 0.f;
        }
        *(float4*)&Ws[lwk][lwc] = wv;
        __syncthreads();

#pragma unroll
        for (int kk = 0; kk < 8; kk++) {
            float4 a0 = *(const float4*)&As[kk][ty * 4];
            float4 a1 = *(const float4*)&As[kk][64 + ty * 4];
            float4 w0 = *(const float4*)&Ws[kk][tx * 4];
            float4 w1 = *(const float4*)&Ws[kk][64 + tx * 4];
            float ar[8] = {a0.x, a0.y, a0.z, a0.w, a1.x, a1.y, a1.z, a1.w};
            float wr[8] = {w0.x, w0.y, w0.z, w0.w, w1.x, w1.y, w1.z, w1.w};
#pragma unroll
            for (int i = 0; i < 8; i++)
#pragma unroll
                for (int j = 0; j < 8; j++)
                    acc[i][j] += ar[i] * wr[j];
        }
        __syncthreads();
    }

#pragma unroll
    for (int i = 0; i < 8; i++) {
        int row = m0 + ((i < 4) ? (ty * 4 + i) : (64 + ty * 4 + i - 4));
        float* Crow = C + (size_t)row * N;
#pragma unroll
        for (int j = 0; j < 8; j++) {
            int col = n0 + ((j < 4) ? (tx * 4 + j) : (64 + tx * 4 + j - 4));
            if (col < N) Crow[col] = acc[i][j] + bias[col];
        }
    }
}

// ================== persistent recurrence kernel =============================
struct RP {
    const float* vgg;
    const float* W_in; const float* b_in;
    const float* Wu0; const float* Wr0; const float* Wc0;
    const float* Wu1; const float* Wr1; const float* Wc1;
    const float* bu1; const float* br1; const float* bc1;
};

// software grid barrier: all 128 blocks co-resident (grid <= 148 SMs)
__device__ __forceinline__ void gridbar(int tid, unsigned* ps) {
    __threadfence();
    __syncthreads();
    if (tid == 0) {
        unsigned ns = *ps ^ 1u;
        *ps = ns;
        if (atomicAdd(&g_bar_count, 1u) == GBLK - 1) {
            *(volatile unsigned*)&g_bar_count = 0;
            __threadfence();
            *(volatile unsigned*)&g_bar_sense = ns;
        } else {
            while (*(volatile unsigned*)&g_bar_sense != ns) { __nanosleep(32); }
        }
        __threadfence();
    }
    __syncthreads();
}

// A fetch: float4 from L2 (__ldcg), optional elementwise-mul second operand
__device__ __forceinline__ float4 ldA4(const float* pA, const float* pB, int k) {
    float4 a = __ldcg((const float4*)(pA + k));
    if (pB) {
        float4 b = __ldcg((const float4*)(pB + k));
        a.x *= b.x; a.y *= b.y; a.z *= b.z; a.w *= b.w;
    }
    return a;
}

// Per-thread row GEMM core: acc[8] += A_row[0:KQ] @ Wslice[0:KQ][8].
// A direct from L2 with a 4-deep float4 register pipeline; W either smem
// (broadcast LDS.128) or direct __ldg (h0's K=4096 case).
template <int KQ, bool WS>
__device__ __forceinline__ void mm8(float (&acc)[8],
    const float* __restrict__ pA, const float* __restrict__ pB,
    const float* __restrict__ sWq, const float* __restrict__ gW)
{
    float4 buf[4];
#pragma unroll
    for (int i = 0; i < 4; i++) buf[i] = ldA4(pA, pB, i * 4);

#pragma unroll 1
    for (int g = 0; g < KQ; g += 16) {
#pragma unroll
        for (int s = 0; s < 4; s++) {
            float4 a = buf[s];
            int kb = g + s * 4 + 16;
            if (kb < KQ) buf[s] = ldA4(pA, pB, kb);
#pragma unroll
            for (int j = 0; j < 4; j++) {
                int k = g + s * 4 + j;
                float4 w0, w1;
                if (WS) {
                    w0 = *(const float4*)(sWq + k * 8);
                    w1 = *(const float4*)(sWq + k * 8 + 4);
                } else {
                    const float* wp = gW + (size_t)k * HIDD;
                    w0 = __ldg((const float4*)wp);
                    w1 = __ldg((const float4*)(wp + 4));
                }
                float av = (j == 0) ? a.x : (j == 1) ? a.y : (j == 2) ? a.z : a.w;
                acc[0] += av * w0.x; acc[1] += av * w0.y;
                acc[2] += av * w0.z; acc[3] += av * w0.w;
                acc[4] += av * w1.x; acc[5] += av * w1.y;
                acc[6] += av * w1.z; acc[7] += av * w1.w;
            }
        }
    }
}

// stage W[k][wcol..wcol+7] for k in [0,K) into sW[k*8 + c]
__device__ __forceinline__ void stageW(float* sW, const float* __restrict__ W,
                                       int wcol, int K, int tid) {
    for (int lin = tid; lin < 2 * K; lin += 256) {
        int k = lin >> 1;
        int c4 = (lin & 1) * 4;
        *(float4*)(sW + k * 8 + c4) =
            __ldg((const float4*)(W + (size_t)k * HIDD + wcol + c4));
    }
}

// cross-q partial reduction through smem (reuses sW region)
template <int MR>
__device__ __forceinline__ void reduceQ(float (&acc)[8], float* sW, int m, int q) {
    const int Q = 256 / MR;
    __syncthreads();
    if (q > 0) {
        float* r = sW + ((size_t)(q - 1) * MR + m) * 8;
        *(float4*)r       = make_float4(acc[0], acc[1], acc[2], acc[3]);
        *(float4*)(r + 4) = make_float4(acc[4], acc[5], acc[6], acc[7]);
    }
    __syncthreads();
    if (q == 0) {
#pragma unroll
        for (int qq = 1; qq < Q; qq++) {
            const float* r = sW + ((size_t)(qq - 1) * MR + m) * 8;
#pragma unroll
            for (int j = 0; j < 8; j++) acc[j] += r[j];
        }
    }
}

__device__ __forceinline__ float sigm(float x) { return 1.f / (1.f + expf(-x)); }

__global__ __launch_bounds__(256, 1) void recur_kernel(RP p) {
    __shared__ float sW[8192];        // 32 KB: W slice / reduction scratch
    __shared__ unsigned s_sense;
    int tid = threadIdx.x, bid = blockIdx.x;
    if (tid == 0) s_sense = *(volatile unsigned*)&g_bar_sense;

    // ---- phase h0: tanh(vgg @ W_in + b_in), MR=64, Q=4, K=4096 (W via L1) ----
    {
        int ct = bid >> 1, rg = bid & 1;
        int c0 = ct * 8, m_base = rg * 64;
        int m = tid & 63, q = tid >> 6;
        const float* pA = p.vgg + (size_t)(m_base + m) * VGGD + q * 1024;
        const float* gW = p.W_in + (size_t)(q * 1024) * HIDD + c0;
        float acc[8] = {0, 0, 0, 0, 0, 0, 0, 0};
        mm8<1024, false>(acc, pA, nullptr, nullptr, gW);
        reduceQ<64>(acc, sW, m, q);
        if (q == 0) {
            int row = m_base + m;
#pragma unroll
            for (int j = 0; j < 8; j++)
                g_h0[row * HIDD + c0 + j] = tanhf(acc[j] + __ldg(p.b_in + c0 + j));
        }
    }
    gridbar(tid, &s_sense);

#pragma unroll 1
    for (int t = 0; t < TT; t++) {
        const float* s0prev = (t == 0) ? g_h0 : g_s0buf[(t - 1) & 1];
        float*       s0cur  = g_s0buf[t & 1];
        const float* s1prev = (t == 0) ? g_h0 : (g_S1 + (size_t)(t - 1) * BB * HIDD);
        float*       s1cur  = g_S1 + (size_t)t * BB * HIDD;
        const float* X0t    = g_X0 + (size_t)t * BB * 3 * HIDD;

        // ---- P1: gu0|gr0 = sigmoid(X0[u|r] + s0prev @ W{u,r}0_bot)  MR=128,Q=2,K=512
        {
            int c0g = bid * 8;
            int half = c0g >= HIDD;
            int wcol = c0g & (HIDD - 1);
            const float* Wg = (half ? p.Wr0 : p.Wu0) + HIDD * HIDD;
            stageW(sW, Wg, wcol, 512, tid);
            __syncthreads();
            int m = tid & 127, q = tid >> 7;
            const float* pA = s0prev + (size_t)m * HIDD + q * 256;
            float acc[8] = {0, 0, 0, 0, 0, 0, 0, 0};
            mm8<256, true>(acc, pA, nullptr, sW + q * 256 * 8, nullptr);
            reduceQ<128>(acc, sW, m, q);
            if (q == 0) {
                float* out = half ? g_gr0 : g_gu0;
                const float* xp = X0t + (size_t)m * 3 * HIDD + c0g;
                float* op = out + (size_t)m * HIDD + wcol;
#pragma unroll
                for (int j = 0; j < 8; j++) op[j] = sigm(acc[j] + __ldg(xp + j));
            }
        }
        gridbar(tid, &s_sense);

        // ---- P2: s0cur = gu0*s0 + (1-gu0)*tanh(X0[c] + (gr0*s0)@Wc0_bot)  MR=64,Q=4,K=512
        {
            int ct = bid >> 1, rg = bid & 1;
            int c0 = ct * 8, m_base = rg * 64;
            stageW(sW, p.Wc0 + HIDD * HIDD, c0, 512, tid);
            __syncthreads();
            int m = tid & 63, q = tid >> 6;
            int row = m_base + m;
            const float* pA = g_gr0 + (size_t)row * HIDD + q * 128;
            const float* pB = s0prev + (size_t)row * HIDD + q * 128;
            float acc[8] = {0, 0, 0, 0, 0, 0, 0, 0};
            mm8<128, true>(acc, pA, pB, sW + q * 128 * 8, nullptr);
            reduceQ<64>(acc, sW, m, q);
            if (q == 0) {
                const float* xp = X0t + (size_t)row * 3 * HIDD + 2 * HIDD + c0;
#pragma unroll
                for (int j = 0; j < 8; j++) {
                    float c  = tanhf(acc[j] + __ldg(xp + j));
                    float gu = __ldcg(g_gu0 + (size_t)row * HIDD + c0 + j);
                    float h  = __ldcg(s0prev + (size_t)row * HIDD + c0 + j);
                    s0cur[(size_t)row * HIDD + c0 + j] = gu * h + (1.f - gu) * c;
                }
            }
        }
        gridbar(tid, &s_sense);

        // ---- P3: gu1|gr1 = sigmoid([s0cur|s1prev] @ W{u,r}1 + b)  MR=128,Q=2,K=1024
        {
            int c0g = bid * 8;
            int half = c0g >= HIDD;
            int wcol = c0g & (HIDD - 1);
            const float* Wg = half ? p.Wr1 : p.Wu1;
            stageW(sW, Wg, wcol, 1024, tid);
            __syncthreads();
            int m = tid & 127, q = tid >> 7;
            const float* pA = (q == 0) ? (s0cur + (size_t)m * HIDD)
                                       : (s1prev + (size_t)m * HIDD);
            float acc[8] = {0, 0, 0, 0, 0, 0, 0, 0};
            mm8<512, true>(acc, pA, nullptr, sW + q * 512 * 8, nullptr);
            reduceQ<128>(acc, sW, m, q);
            if (q == 0) {
                const float* b = half ? p.br1 : p.bu1;
                float* out = half ? g_gr1 : g_gu1;
                float* op = out + (size_t)m * HIDD + wcol;
#pragma unroll
                for (int j = 0; j < 8; j++) op[j] = sigm(acc[j] + __ldg(b + wcol + j));
            }
        }
        gridbar(tid, &s_sense);

        // ---- P4: s1cur = gu1*s1 + (1-gu1)*tanh([s0cur|gr1*s1]@Wc1 + bc1)  MR=64,Q=4,K=1024
        {
            int ct = bid >> 1, rg = bid & 1;
            int c0 = ct * 8, m_base = rg * 64;
            stageW(sW, p.Wc1, c0, 1024, tid);
            __syncthreads();
            int m = tid & 63, q = tid >> 6;
            int row = m_base + m;
            const float* pA;
            const float* pB = nullptr;
            if (q < 2) {
                pA = s0cur + (size_t)row * HIDD + q * 256;
            } else {
                pA = g_gr1 + (size_t)row * HIDD + (q - 2) * 256;
                pB = s1prev + (size_t)row * HIDD + (q - 2) * 256;
            }
            float acc[8] = {0, 0, 0, 0, 0, 0, 0, 0};
            mm8<256, true>(acc, pA, pB, sW + q * 256 * 8, nullptr);
            reduceQ<64>(acc, sW, m, q);
            if (q == 0) {
#pragma unroll
                for (int j = 0; j < 8; j++) {
                    float c  = tanhf(acc[j] + __ldg(p.bc1 + c0 + j));
                    float gu = __ldcg(g_gu1 + (size_t)row * HIDD + c0 + j);
                    float h  = __ldcg(s1prev + (size_t)row * HIDD + c0 + j);
                    s1cur[(size_t)row * HIDD + c0 + j] = gu * h + (1.f - gu) * c;
                }
            }
        }
        gridbar(tid, &s_sense);
    }
}

// ---------------- final state write ------------------------------------------
__global__ void write_state(float* __restrict__ out) {
    int idx = blockIdx.x * blockDim.x + threadIdx.x;
    if (idx < BB * HIDD) {
        size_t base = (size_t)BB * TT * VOCAB;
        out[base + idx] = g_s0buf[(TT - 1) & 1][idx];
        out[base + BB * HIDD + idx] = g_S1[(size_t)(TT - 1) * BB * HIDD + idx];
    }
}

// ---------------- host driver -------------------------------------------------
template <typename Sym>
static float* sym(Sym& s) {
    void* p = nullptr;
    cudaGetSymbolAddress(&p, s);
    return (float*)p;
}

extern "C" void kernel_launch(void* const* d_in, const int* in_sizes, int n_in,
                              void* d_out, int out_size) {
    const float* vgg     = (const float*)d_in[0];
    const int*   xTokens = (const int*)d_in[1];
    int i = 2;
    if (n_in >= 20 && in_sizes[2] == 1) i = 3;   // skip is_train scalar
    const float* emb   = (const float*)d_in[i++];
    const float* W_in  = (const float*)d_in[i++];
    const float* b_in  = (const float*)d_in[i++];
    const float* Wu0   = (const float*)d_in[i++];
    const float* bu0   = (const float*)d_in[i++];
    const float* Wr0   = (const float*)d_in[i++];
    const float* br0   = (const float*)d_in[i++];
    const float* Wc0   = (const float*)d_in[i++];
    const float* bc0   = (const float*)d_in[i++];
    const float* Wu1   = (const float*)d_in[i++];
    const float* bu1   = (const float*)d_in[i++];
    const float* Wr1   = (const float*)d_in[i++];
    const float* br1   = (const float*)d_in[i++];
    const float* Wc1   = (const float*)d_in[i++];
    const float* bc1   = (const float*)d_in[i++];
    const float* W_out = (const float*)d_in[i++];
    const float* b_out = (const float*)d_in[i++];
    float* out = (float*)d_out;

    float* pE     = sym(g_E);
    float* pX0    = sym(g_X0);
    float* pS1    = sym(g_S1);
    float* pW0top = sym(g_W0top);
    float* pB0top = sym(g_b0top);

    // 1) pack layer-0 top weights + biases
    pack_w0top<<<(HIDD * 3 * HIDD + 255) / 256, 256>>>(Wu0, Wr0, Wc0, bu0, br0, bc0);

    // 2) embedding gather
    embed_gather<<<TT * BB, 128>>>(emb, xTokens);

    // 3) X0 = E_all @ W0top + b0top   [3200,512]@[512,1536]
    sgemm_big<0><<<dim3(3 * HIDD / 128, TT * BB / 128), 256>>>(
        pE, pW0top, pB0top, pX0, TT * BB, 3 * HIDD, HIDD);

    // 4) persistent recurrence (h0 + 25 GRU steps, software grid barriers)
    {
        RP rp;
        rp.vgg = vgg; rp.W_in = W_in; rp.b_in = b_in;
        rp.Wu0 = Wu0; rp.Wr0 = Wr0; rp.Wc0 = Wc0;
        rp.Wu1 = Wu1; rp.Wr1 = Wr1; rp.Wc1 = Wc1;
        rp.bu1 = bu1; rp.br1 = br1; rp.bc1 = bc1;
        recur_kernel<<<GBLK, 256>>>(rp);
    }

    // 5) logits = S1 @ W_out + b_out, output rows in (b*T+t) order via A-remap
    sgemm_big<1><<<dim3((VOCAB + 127) / 128, TT * BB / 128), 256>>>(
        pS1, W_out, b_out, out, TT * BB, VOCAB, HIDD);

    // 6) final state [2, B, HID]
    write_state<<<(BB * HIDD + 255) / 256, 256>>>(out);
}